// round 3
// baseline (speedup 1.0000x reference)
#include <cuda_runtime.h>

typedef unsigned long long u64;

#define VOCAB   10000
#define EMB     256
#define UNITS   128
#define NG      512        // 4 * UNITS, gate order i,f,c,o
#define BATCH   256
#define SEQ     1024

// Wr split: k rows [0,KR) live in registers, [KR,128) in shared memory.
#define KR      80
#define KS      48
#define KRP     40         // KR/2  (f32x2 pairs along k)
#define KSP     24         // KS/2

#define NTHREADS 256
#define NBLOCKS  128       // 2 batch rows per block

// Precomputed gate table: G[v][c] = sum_e emb[v][e]*Wk[e][c] + b[c]   (20.5 MB)
__device__ float g_G[VOCAB * NG];

// ---------------- f32x2 helpers (Blackwell packed fp32) ----------------
__device__ __forceinline__ u64 fma2(u64 a, u64 b, u64 c) {
    u64 d;
    asm("fma.rn.f32x2 %0, %1, %2, %3;" : "=l"(d) : "l"(a), "l"(b), "l"(c));
    return d;
}
__device__ __forceinline__ u64 pk2(float x, float y) {
    u64 r;
    asm("mov.b64 %0, {%1, %2};" : "=l"(r) : "f"(x), "f"(y));
    return r;
}
__device__ __forceinline__ float2 upk2(u64 v) {
    float2 r;
    asm("mov.b64 {%0, %1}, %2;" : "=f"(r.x), "=f"(r.y) : "l"(v));
    return r;
}
__device__ __forceinline__ float sigmoidf(float x) {
    return __fdividef(1.0f, 1.0f + __expf(-x));
}

// ---------------- Kernel 1: G = emb @ Wk + b  (2.6 GFLOP) ----------------
#define VB 16
__global__ void __launch_bounds__(512)
gbuild_kernel(const float* __restrict__ emb, const float* __restrict__ Wk,
              const float* __restrict__ b)
{
    __shared__ float es[VB][EMB];           // 16 KB tile of embedding rows
    const int c  = threadIdx.x;             // column 0..511
    const int v0 = blockIdx.x * VB;

    for (int i = c; i < VB * EMB; i += 512)
        es[i / EMB][i % EMB] = emb[v0 * EMB + i];
    __syncthreads();

    float acc[VB];
#pragma unroll
    for (int v = 0; v < VB; v++) acc[v] = 0.0f;

    for (int e = 0; e < EMB; e += 4) {
        const float w0 = Wk[(e + 0) * NG + c];
        const float w1 = Wk[(e + 1) * NG + c];
        const float w2 = Wk[(e + 2) * NG + c];
        const float w3 = Wk[(e + 3) * NG + c];
#pragma unroll
        for (int v = 0; v < VB; v++) {
            float4 ev = *(const float4*)&es[v][e];
            acc[v] += ev.x * w0 + ev.y * w1 + ev.z * w2 + ev.w * w3;
        }
    }
    const float bc = b[c];
#pragma unroll
    for (int v = 0; v < VB; v++)
        g_G[(v0 + v) * NG + c] = acc[v] + bc;
}

// ---------------- Kernel 2: persistent LSTM recurrence ----------------
// Each block owns 2 batch rows for all 1024 steps. 256 threads.
// Thread j owns gate-columns {j, j+256} of z for both rows (full k in one
// thread: no cross-thread reduction), and LSTM unit (u=j%128, row=j/128)
// for the nonlinearity + cell state.
//
// Dynamic smem layout:
//   Ws   : [KSP][NG] u64 pairs (Wr[KR+2kk][col], Wr[KR+2kk+1][col])  96 KB
//   h_s  : [2][UNITS] float                                           1 KB
//   z_s  : [2][NG] float                                              4 KB
//   xs   : [2][SEQ] int tokens                                        8 KB
#define WS_BYTES (KSP * NG * 8)
#define H_BYTES  (2 * UNITS * 4)
#define Z_BYTES  (2 * NG * 4)
#define X_BYTES  (2 * SEQ * 4)
#define SMEM_TOTAL (WS_BYTES + H_BYTES + Z_BYTES + X_BYTES)

__global__ void __launch_bounds__(NTHREADS, 1)
lstm_kernel(const int* __restrict__ x, const float* __restrict__ Wr,
            const float* __restrict__ Wd, const float* __restrict__ bd,
            float* __restrict__ out)
{
    extern __shared__ char smem[];
    u64*   Ws  = (u64*)smem;
    float* h_s = (float*)(smem + WS_BYTES);
    float* z_s = (float*)(smem + WS_BYTES + H_BYTES);
    int*   xs  = (int*)  (smem + WS_BYTES + H_BYTES + Z_BYTES);

    const int j   = threadIdx.x;       // 0..255
    const int blk = blockIdx.x;        // 0..127

    // ---- one-time setup ----
    // tokens for this block's 2 rows
    for (int i = j; i < 2 * SEQ; i += NTHREADS) {
        int row = i >> 10, tt = i & (SEQ - 1);
        xs[i] = x[(blk * 2 + row) * SEQ + tt];
    }
    // register-resident weights: cols c0=j, c1=j+256, k in [0,KR)
    u64 w0[KRP], w1[KRP];
#pragma unroll
    for (int kk = 0; kk < KRP; kk++) {
        w0[kk] = pk2(Wr[(2 * kk) * NG + j],       Wr[(2 * kk + 1) * NG + j]);
        w1[kk] = pk2(Wr[(2 * kk) * NG + j + 256], Wr[(2 * kk + 1) * NG + j + 256]);
    }
    // smem-resident weights: k in [KR,128)
    for (int i = j; i < KSP * NG; i += NTHREADS) {
        int kk = i / NG, col = i % NG;
        int k  = KR + 2 * kk;
        Ws[kk * NG + col] = pk2(Wr[k * NG + col], Wr[(k + 1) * NG + col]);
    }
    // h = 0
    for (int i = j; i < 2 * UNITS; i += NTHREADS) h_s[i] = 0.0f;
    __syncthreads();

    const int u   = j & (UNITS - 1);
    const int row = j >> 7;
    float c_state = 0.0f;

    const float* h0p = h_s;             // row 0 hidden state
    const float* h1p = h_s + UNITS;     // row 1

    for (int t = 0; t < SEQ; t++) {
        // prefetch this step's gate-table gathers (consumed after phase A)
        const int tok = xs[row * SEQ + t];
        const float* gr = g_G + tok * NG + u;
        const float xg0 = gr[0];
        const float xg1 = gr[128];
        const float xg2 = gr[256];
        const float xg3 = gr[384];

        // ---- phase A: partial z = h @ Wr for my two columns, both rows ----
        // Weight pair w[kk] covers k-rows {2kk, 2kk+1}; with kk stepping by 2,
        // each iteration consumes k-rows {2kk..2kk+3} == h[2kk..2kk+3].
        u64 acc00 = 0ull, acc01 = 0ull, acc10 = 0ull, acc11 = 0ull;
#pragma unroll
        for (int kk = 0; kk < KRP; kk += 2) {
            ulonglong2 hv0 = *(const ulonglong2*)(h0p + 2 * kk);  // h[2kk..2kk+3]
            ulonglong2 hv1 = *(const ulonglong2*)(h1p + 2 * kk);
            acc00 = fma2(w0[kk],     hv0.x, acc00);
            acc00 = fma2(w0[kk + 1], hv0.y, acc00);
            acc01 = fma2(w0[kk],     hv1.x, acc01);
            acc01 = fma2(w0[kk + 1], hv1.y, acc01);
            acc10 = fma2(w1[kk],     hv0.x, acc10);
            acc10 = fma2(w1[kk + 1], hv0.y, acc10);
            acc11 = fma2(w1[kk],     hv1.x, acc11);
            acc11 = fma2(w1[kk + 1], hv1.y, acc11);
        }
#pragma unroll
        for (int kk = 0; kk < KSP; kk += 2) {
            // Ws pair kk covers k-rows {KR+2kk, KR+2kk+1} -> h[KR+2kk..KR+2kk+3]
            ulonglong2 hv0 = *(const ulonglong2*)(h0p + KR + 2 * kk);
            ulonglong2 hv1 = *(const ulonglong2*)(h1p + KR + 2 * kk);
            u64 wa0 = Ws[kk * NG + j];
            u64 wb0 = Ws[(kk + 1) * NG + j];
            u64 wa1 = Ws[kk * NG + j + 256];
            u64 wb1 = Ws[(kk + 1) * NG + j + 256];
            acc00 = fma2(wa0, hv0.x, acc00);
            acc00 = fma2(wb0, hv0.y, acc00);
            acc01 = fma2(wa0, hv1.x, acc01);
            acc01 = fma2(wb0, hv1.y, acc01);
            acc10 = fma2(wa1, hv0.x, acc10);
            acc10 = fma2(wb1, hv0.y, acc10);
            acc11 = fma2(wa1, hv1.x, acc11);
            acc11 = fma2(wb1, hv1.y, acc11);
        }
        {
            float2 a00 = upk2(acc00), a01 = upk2(acc01);
            float2 a10 = upk2(acc10), a11 = upk2(acc11);
            z_s[0 * NG + j]       = a00.x + a00.y;
            z_s[1 * NG + j]       = a01.x + a01.y;
            z_s[0 * NG + j + 256] = a10.x + a10.y;
            z_s[1 * NG + j + 256] = a11.x + a11.y;
        }
        __syncthreads();

        // ---- phase C: gates + cell update for my (u,row) unit ----
        const float zi = z_s[row * NG + u]       + xg0;
        const float zf = z_s[row * NG + u + 128] + xg1;
        const float zc = z_s[row * NG + u + 256] + xg2;
        const float zo = z_s[row * NG + u + 384] + xg3;
        const float ig = sigmoidf(zi);
        const float fg = sigmoidf(zf);
        const float gg = fmaxf(zc, 0.0f);        // activation = relu
        const float og = sigmoidf(zo);
        c_state = fg * c_state + ig * gg;
        const float hn = og * fmaxf(c_state, 0.0f);
        h_s[row * UNITS + u] = hn;
        __syncthreads();
    }

    // ---- dense head: out[row] = h @ Wd + bd ----
    if (j < 4) {
        const int rr = j >> 1, oc = j & 1;
        float acc = bd[oc];
        for (int uu = 0; uu < UNITS; uu++)
            acc += h_s[rr * UNITS + uu] * Wd[uu * 2 + oc];
        out[(blk * 2 + rr) * 2 + oc] = acc;
    }
}

// ---------------- launch ----------------
extern "C" void kernel_launch(void* const* d_in, const int* in_sizes, int n_in,
                              void* d_out, int out_size)
{
    const int*   x   = 0;
    const float *emb = 0, *Wk = 0, *Wr = 0, *bb = 0, *Wd = 0, *bd = 0;
    for (int i = 0; i < n_in; i++) {
        switch (in_sizes[i]) {                       // all sizes are distinct
            case BATCH * SEQ: x   = (const int*)  d_in[i]; break;  // 262144
            case VOCAB * EMB: emb = (const float*)d_in[i]; break;  // 2560000
            case EMB * NG:    Wk  = (const float*)d_in[i]; break;  // 131072
            case UNITS * NG:  Wr  = (const float*)d_in[i]; break;  // 65536
            case NG:          bb  = (const float*)d_in[i]; break;  // 512
            case UNITS * 2:   Wd  = (const float*)d_in[i]; break;  // 256
            case 2:           bd  = (const float*)d_in[i]; break;
        }
    }

    gbuild_kernel<<<VOCAB / VB, 512>>>(emb, Wk, bb);

    cudaFuncSetAttribute(lstm_kernel,
                         cudaFuncAttributeMaxDynamicSharedMemorySize, SMEM_TOTAL);
    lstm_kernel<<<NBLOCKS, NTHREADS, SMEM_TOTAL>>>(x, Wr, Wd, bd, (float*)d_out);
}